// round 1
// baseline (speedup 1.0000x reference)
#include <cuda_runtime.h>
#include <cstdint>

#define BATCH 128
#define MEMSZ 200
#define SENT  50
#define DIM   128
#define VOCAB 50000
#define HOPS  3

// ---------------- scratch (device globals; no allocation in kernel_launch) ----
__device__ float g_m[4ll * BATCH * MEMSZ * DIM];   // m_k for tables 0..3
__device__ float g_u[BATCH * DIM];
__device__ int   g_is64;

// ---------------- position encoding (closed form) ----------------------------
// enc[s][d]: built as [D,S] with i=d+1, j=s+1:
//   e = 1 + 4*(i-(D+1)/2)*(j-(S+1)/2)/D/S ; last sentence position forced to 1.
__device__ __forceinline__ float enc_val(int s, int d) {
    if (s == SENT - 1) return 1.0f;
    float ed = (float)(d + 1) - 0.5f * (DIM + 1);   // d+1 - 64.5
    float es = (float)(s + 1) - 0.5f * (SENT + 1);  // s+1 - 25.5
    return 1.0f + 4.0f * ed * es / (float)DIM / (float)SENT;
}

__device__ __forceinline__ int load_idx(const void* p, long long i, int is64) {
    if (is64) return (int)__ldg(((const long long*)p) + i);
    return __ldg(((const int*)p) + i);
}

// ---------------- dtype sniff: int64 little-endian => odd 32-bit words all 0 --
__global__ void sniff_kernel(const int* story32, int n32) {
    if (threadIdx.x == 0 && blockIdx.x == 0) {
        int any = 0;
        int lim = n32 < 4001 ? n32 : 4001;
        for (int i = 1; i < lim; i += 2) any |= story32[i];
        g_is64 = (any == 0) ? 1 : 0;
    }
}

// ---------------- m_k[b,m,d] = sum_s C[k][story[b,m,s]][d] * enc(s,d) --------
// grid.x = B*M, grid.y = table k ; block = 128 threads (one per d)
__global__ void m_kernel(const void* __restrict__ story, const float* __restrict__ C) {
    int bm = blockIdx.x;
    int k  = blockIdx.y;
    int d  = threadIdx.x;

    __shared__ int s_idx[SENT];
    int is64 = g_is64;
    if (threadIdx.x < SENT)
        s_idx[threadIdx.x] = load_idx(story, (long long)bm * SENT + threadIdx.x, is64);
    __syncthreads();

    const float* tab = C + (long long)k * VOCAB * DIM;
    float ed = (float)(d + 1) - 0.5f * (DIM + 1);
    const float cc = 4.0f / ((float)DIM * (float)SENT);

    float acc = 0.0f;
#pragma unroll
    for (int s = 0; s < SENT; ++s) {
        float w = (s == SENT - 1) ? 1.0f
                 : fmaf(cc * ((float)(s + 1) - 0.5f * (SENT + 1)), ed, 1.0f);
        float v = __ldg(&tab[(long long)s_idx[s] * DIM + d]);
        acc = fmaf(v, w, acc);
    }
    g_m[((long long)k * (BATCH * MEMSZ) + bm) * DIM + d] = acc;
}

// ---------------- u0[b,d] = sum_s C[0][query[b,s]][d] * enc(s,d) -------------
__global__ void u0_kernel(const void* __restrict__ query, const float* __restrict__ C) {
    int b = blockIdx.x;
    int d = threadIdx.x;
    __shared__ int s_idx[SENT];
    int is64 = g_is64;
    if (threadIdx.x < SENT)
        s_idx[threadIdx.x] = load_idx(query, (long long)b * SENT + threadIdx.x, is64);
    __syncthreads();

    float acc = 0.0f;
#pragma unroll
    for (int s = 0; s < SENT; ++s) {
        float w = enc_val(s, d);
        acc = fmaf(__ldg(&C[(long long)s_idx[s] * DIM + d]), w, acc);
    }
    g_u[b * DIM + d] = acc;
}

// ---------------- one hop: attention + softmax + gated update ----------------
// grid = B blocks, 256 threads
__global__ void hop_kernel(int hop, const float* __restrict__ Tw, const float* __restrict__ Tb) {
    int b   = blockIdx.x;
    int tid = threadIdx.x;
    int lane = tid & 31, warp = tid >> 5;

    __shared__ float u_sh[DIM];
    __shared__ float prob[MEMSZ];
    __shared__ float red[256];

    if (tid < DIM) u_sh[tid] = g_u[b * DIM + tid];
    __syncthreads();

    const float* mA = g_m + ((long long)hop       * BATCH * MEMSZ + (long long)b * MEMSZ) * DIM;
    const float* mC = g_m + ((long long)(hop + 1) * BATCH * MEMSZ + (long long)b * MEMSZ) * DIM;

    // scores: one warp per m (8 warps stride over 200 rows), coalesced row reads
    for (int m = warp; m < MEMSZ; m += 8) {
        const float* row = mA + (long long)m * DIM;
        float s = 0.0f;
#pragma unroll
        for (int dd = lane; dd < DIM; dd += 32) s = fmaf(row[dd], u_sh[dd], s);
#pragma unroll
        for (int off = 16; off; off >>= 1) s += __shfl_xor_sync(0xffffffffu, s, off);
        if (lane == 0) prob[m] = s;
    }
    __syncthreads();

    // softmax over MEMSZ
    float v = (tid < MEMSZ) ? prob[tid] : -1e30f;
    red[tid] = v; __syncthreads();
#pragma unroll
    for (int s = 128; s > 0; s >>= 1) {
        if (tid < s) red[tid] = fmaxf(red[tid], red[tid + s]);
        __syncthreads();
    }
    float mx = red[0]; __syncthreads();
    float e = (tid < MEMSZ) ? __expf(prob[tid] - mx) : 0.0f;
    // use accurate expf for safety of tolerance
    e = (tid < MEMSZ) ? expf(prob[tid] - mx) : 0.0f;
    red[tid] = e; __syncthreads();
#pragma unroll
    for (int s = 128; s > 0; s >>= 1) {
        if (tid < s) red[tid] += red[tid + s];
        __syncthreads();
    }
    float inv = 1.0f / red[0];
    if (tid < MEMSZ) prob[tid] = e * inv;
    __syncthreads();

    // o[d] = sum_m prob[m]*mC[m][d];   t = sigmoid(Tw[d,:]·u + Tb[d]); update u
    if (tid < DIM) {
        int d = tid;
        float o = 0.0f;
#pragma unroll 4
        for (int m = 0; m < MEMSZ; ++m)
            o = fmaf(prob[m], mC[(long long)m * DIM + d], o);

        float t = __ldg(&Tb[d]);
        const float* twrow = Tw + (long long)d * DIM;
#pragma unroll 8
        for (int e2 = 0; e2 < DIM; ++e2) t = fmaf(__ldg(&twrow[e2]), u_sh[e2], t);
        t = 1.0f / (1.0f + expf(-t));

        g_u[b * DIM + d] = (1.0f - t) * u_sh[d] + o * t;
    }
}

// ---------------- a_hat[b,v] = sum_d u[b,d]*C3[v,d] ---------------------------
// register-tiled SGEMM: block = 256 threads (16x16), tile 128v x 128b, DK=32
#define GV 128
#define DK 32
__global__ void out_gemm(const float* __restrict__ C3, float* __restrict__ out) {
    __shared__ float Csh[DK][GV + 4];
    __shared__ float Ush[DK][BATCH + 4];

    int tid = threadIdx.x;
    int tx = tid & 15, ty = tid >> 4;
    int v0 = blockIdx.x * GV;

    float acc[8][8];
#pragma unroll
    for (int j = 0; j < 8; ++j)
#pragma unroll
        for (int i = 0; i < 8; ++i) acc[j][i] = 0.0f;

    for (int k0 = 0; k0 < DIM; k0 += DK) {
#pragma unroll
        for (int i = tid; i < DK * GV; i += 256) {
            int kk = i & (DK - 1);
            int vv = i >> 5;
            int v = v0 + vv;
            Csh[kk][vv] = (v < VOCAB) ? __ldg(&C3[(long long)v * DIM + k0 + kk]) : 0.0f;
            Ush[kk][vv] = g_u[vv * DIM + k0 + kk];
        }
        __syncthreads();
#pragma unroll
        for (int kk = 0; kk < DK; ++kk) {
            float a[8], bb[8];
#pragma unroll
            for (int i = 0; i < 8; ++i) a[i]  = Csh[kk][tx * 8 + i];
#pragma unroll
            for (int j = 0; j < 8; ++j) bb[j] = Ush[kk][ty * 8 + j];
#pragma unroll
            for (int j = 0; j < 8; ++j)
#pragma unroll
                for (int i = 0; i < 8; ++i) acc[j][i] = fmaf(a[i], bb[j], acc[j][i]);
        }
        __syncthreads();
    }

#pragma unroll
    for (int j = 0; j < 8; ++j) {
        int b = ty * 8 + j;
#pragma unroll
        for (int i = 0; i < 8; ++i) {
            int v = v0 + tx * 8 + i;
            if (v < VOCAB) out[(long long)b * VOCAB + v] = acc[j][i];
        }
    }
}

// ---------------- launch ------------------------------------------------------
extern "C" void kernel_launch(void* const* d_in, const int* in_sizes, int n_in,
                              void* d_out, int out_size) {
    const void*  story = d_in[0];                 // [B,M,S] int32 or int64
    const void*  query = d_in[1];                 // [B,S]
    const float* C     = (const float*)d_in[2];   // [4,V,D]
    const float* Tw    = (const float*)d_in[3];   // [D,D]
    const float* Tb    = (const float*)d_in[4];   // [D]
    float* out = (float*)d_out;                   // [B,V]

    // dtype sniff (deterministic on input contents)
    sniff_kernel<<<1, 32>>>((const int*)story, in_sizes[0]);

    // all 4 m_k tables up-front (m_A of hop h+1 == m_C of hop h: 4 passes not 6)
    m_kernel<<<dim3(BATCH * MEMSZ, 4), DIM>>>(story, C);

    // u0
    u0_kernel<<<BATCH, DIM>>>(query, C);

    // hops
    for (int h = 0; h < HOPS; ++h)
        hop_kernel<<<BATCH, 256>>>(h, Tw, Tb);

    // final projection onto vocab
    int gv = (VOCAB + GV - 1) / GV;
    out_gemm<<<gv, 256>>>(C + 3ll * VOCAB * DIM, out);
}

// round 3
// speedup vs baseline: 1.4782x; 1.4782x over previous
#include <cuda_runtime.h>
#include <cstdint>

#define BATCH 128
#define MEMSZ 200
#define SENT  50
#define DIM   128
#define VOCAB 50000
#define HOPS  3

typedef long long ll;

// ---------------- scratch (device globals; no allocation in kernel_launch) ----
__device__ float g_m[4ll * BATCH * MEMSZ * DIM];   // m_k for tables 0..3
__device__ float g_u[BATCH * DIM];
__device__ int   g_is64;

__device__ __forceinline__ int load_idx(const void* p, ll i, int is64) {
    if (is64) return (int)__ldg(((const ll*)p) + i);
    return __ldg(((const int*)p) + i);
}

// ---------------- dtype sniff: int64 little-endian => odd 32-bit words all 0 --
__global__ void sniff_kernel(const int* __restrict__ story32, int n32) {
    __shared__ int any;
    if (threadIdx.x == 0) any = 0;
    __syncthreads();
    int lim = n32 < 20001 ? n32 : 20001;
    int local = 0;
    for (int i = 1 + 2 * (int)threadIdx.x; i < lim; i += 2 * (int)blockDim.x)
        local |= story32[i];
    if (local) atomicOr(&any, 1);
    __syncthreads();
    if (threadIdx.x == 0) g_is64 = (any == 0) ? 1 : 0;
}

// ---------------- m_k[b,m,d] = sum_s C_k[story[b,m,s]][d] * enc(s,d) ---------
// enc(s,d) = 1 + cc*ed(d)*es(s), with es(S-1)=0 (last column forced to 1).
// block = 128 threads (4 warps). Warp w handles rows s = w, w+4, ...
// Each lane owns d-chunk [lane*4, lane*4+4) and loads the row as float4.
__global__ void m_kernel(const void* __restrict__ story, const float* __restrict__ tab,
                         float* __restrict__ mout) {
    int bm   = blockIdx.x;
    int tid  = threadIdx.x;
    int lane = tid & 31, w = tid >> 5;

    __shared__ int    s_idx[SENT];
    __shared__ float4 part[3][32];

    int is64 = g_is64;
    if (tid < SENT) s_idx[tid] = load_idx(story, (ll)bm * SENT + tid, is64);
    __syncthreads();

    const int d0 = lane * 4;
    const float cc  = 4.0f / ((float)DIM * (float)SENT);
    const float ed0 = (float)(d0 + 1) - 64.5f;
    const float ed1 = ed0 + 1.0f, ed2 = ed0 + 2.0f, ed3 = ed0 + 3.0f;

    float4 acc = make_float4(0.f, 0.f, 0.f, 0.f);
    for (int s = w; s < SENT; s += 4) {
        float es = (s == SENT - 1) ? 0.0f : ((float)(s + 1) - 25.5f);
        float ce = cc * es;
        float4 v = *(const float4*)&tab[(ll)s_idx[s] * DIM + d0];
        acc.x = fmaf(v.x, fmaf(ce, ed0, 1.0f), acc.x);
        acc.y = fmaf(v.y, fmaf(ce, ed1, 1.0f), acc.y);
        acc.z = fmaf(v.z, fmaf(ce, ed2, 1.0f), acc.z);
        acc.w = fmaf(v.w, fmaf(ce, ed3, 1.0f), acc.w);
    }
    if (w > 0) part[w - 1][lane] = acc;
    __syncthreads();
    if (w == 0) {
        float4 p0 = part[0][lane], p1 = part[1][lane], p2 = part[2][lane];
        acc.x += p0.x + p1.x + p2.x;
        acc.y += p0.y + p1.y + p2.y;
        acc.z += p0.z + p1.z + p2.z;
        acc.w += p0.w + p1.w + p2.w;
        *(float4*)&mout[(ll)bm * DIM + d0] = acc;
    }
}

// ---------------- u0[b,d] = sum_s C0[query[b,s]][d] * enc(s,d) ---------------
__global__ void u0_kernel(const void* __restrict__ query, const float* __restrict__ C) {
    int b    = blockIdx.x;
    int tid  = threadIdx.x;
    int lane = tid & 31, w = tid >> 5;

    __shared__ int    s_idx[SENT];
    __shared__ float4 part[3][32];

    int is64 = g_is64;
    if (tid < SENT) s_idx[tid] = load_idx(query, (ll)b * SENT + tid, is64);
    __syncthreads();

    const int d0 = lane * 4;
    const float cc  = 4.0f / ((float)DIM * (float)SENT);
    const float ed0 = (float)(d0 + 1) - 64.5f;
    const float ed1 = ed0 + 1.0f, ed2 = ed0 + 2.0f, ed3 = ed0 + 3.0f;

    float4 acc = make_float4(0.f, 0.f, 0.f, 0.f);
    for (int s = w; s < SENT; s += 4) {
        float es = (s == SENT - 1) ? 0.0f : ((float)(s + 1) - 25.5f);
        float ce = cc * es;
        float4 v = *(const float4*)&C[(ll)s_idx[s] * DIM + d0];
        acc.x = fmaf(v.x, fmaf(ce, ed0, 1.0f), acc.x);
        acc.y = fmaf(v.y, fmaf(ce, ed1, 1.0f), acc.y);
        acc.z = fmaf(v.z, fmaf(ce, ed2, 1.0f), acc.z);
        acc.w = fmaf(v.w, fmaf(ce, ed3, 1.0f), acc.w);
    }
    if (w > 0) part[w - 1][lane] = acc;
    __syncthreads();
    if (w == 0) {
        float4 p0 = part[0][lane], p1 = part[1][lane], p2 = part[2][lane];
        acc.x += p0.x + p1.x + p2.x;
        acc.y += p0.y + p1.y + p2.y;
        acc.z += p0.z + p1.z + p2.z;
        acc.w += p0.w + p1.w + p2.w;
        *(float4*)&g_u[b * DIM + d0] = acc;
    }
}

// ---------------- one hop: attention + softmax + gated update ----------------
// grid = B blocks, 512 threads (16 warps), float4 loads throughout.
__global__ __launch_bounds__(512, 1)
void hop_kernel(int hop, const float* __restrict__ Tw, const float* __restrict__ Tb) {
    int b    = blockIdx.x;
    int tid  = threadIdx.x;
    int lane = tid & 31, w = tid >> 5;   // 16 warps

    __shared__ float  u_sh[DIM];
    __shared__ float  prob[MEMSZ];
    __shared__ float  red[512];
    __shared__ float4 opart[16][32];
    __shared__ float  o_sh[DIM];

    if (tid < DIM) u_sh[tid] = g_u[b * DIM + tid];
    __syncthreads();

    const float* mA = g_m + ((ll)hop       * BATCH * MEMSZ + (ll)b * MEMSZ) * DIM;
    const float* mC = g_m + ((ll)(hop + 1) * BATCH * MEMSZ + (ll)b * MEMSZ) * DIM;

    // ---- scores: one warp per memory row (vectorized dot) ----
    float4 us = *(const float4*)&u_sh[lane * 4];
    for (int m = w; m < MEMSZ; m += 16) {
        float4 v = *(const float4*)&mA[(ll)m * DIM + lane * 4];
        float s = v.x * us.x + v.y * us.y + v.z * us.z + v.w * us.w;
#pragma unroll
        for (int off = 16; off; off >>= 1) s += __shfl_xor_sync(0xffffffffu, s, off);
        if (lane == 0) prob[m] = s;
    }
    __syncthreads();

    // ---- softmax over MEMSZ (512-wide tree) ----
    float val = (tid < MEMSZ) ? prob[tid] : -1e30f;
    red[tid] = val; __syncthreads();
#pragma unroll
    for (int s = 256; s > 0; s >>= 1) {
        if (tid < s) red[tid] = fmaxf(red[tid], red[tid + s]);
        __syncthreads();
    }
    float mx = red[0]; __syncthreads();
    float e = (tid < MEMSZ) ? expf(val - mx) : 0.0f;
    red[tid] = e; __syncthreads();
#pragma unroll
    for (int s = 256; s > 0; s >>= 1) {
        if (tid < s) red[tid] += red[tid + s];
        __syncthreads();
    }
    float inv = 1.0f / red[0];
    if (tid < MEMSZ) prob[tid] = e * inv;
    __syncthreads();

    // ---- o[d] = sum_m prob[m]*mC[m][d]: warp-partitioned over m ----
    float4 o = make_float4(0.f, 0.f, 0.f, 0.f);
    for (int m = w; m < MEMSZ; m += 16) {
        float p = prob[m];
        float4 v = *(const float4*)&mC[(ll)m * DIM + lane * 4];
        o.x = fmaf(p, v.x, o.x); o.y = fmaf(p, v.y, o.y);
        o.z = fmaf(p, v.z, o.z); o.w = fmaf(p, v.w, o.w);
    }
    opart[w][lane] = o;
    __syncthreads();
    if (tid < 32) {
        float4 s = make_float4(0.f, 0.f, 0.f, 0.f);
#pragma unroll
        for (int ww = 0; ww < 16; ++ww) {
            float4 p = opart[ww][tid];
            s.x += p.x; s.y += p.y; s.z += p.z; s.w += p.w;
        }
        *(float4*)&o_sh[tid * 4] = s;
    }
    __syncthreads();

    // ---- gate: t = sigmoid(Tw[d,:]·u + Tb[d]); 4 threads per d ----
    {
        int d = tid >> 2, q = tid & 3;
        const float* twrow = Tw + (ll)d * DIM + q * 32;
        float part = 0.0f;
#pragma unroll
        for (int j = 0; j < 32; j += 4) {
            float4 tv = *(const float4*)&twrow[j];
            float4 uv = *(const float4*)&u_sh[q * 32 + j];
            part = fmaf(tv.x, uv.x, part); part = fmaf(tv.y, uv.y, part);
            part = fmaf(tv.z, uv.z, part); part = fmaf(tv.w, uv.w, part);
        }
        red[tid] = part;
    }
    __syncthreads();
    if ((tid & 3) == 0) {
        int d = tid >> 2;
        float t = red[tid] + red[tid + 1] + red[tid + 2] + red[tid + 3] + __ldg(&Tb[d]);
        t = 1.0f / (1.0f + expf(-t));
        g_u[b * DIM + d] = (1.0f - t) * u_sh[d] + o_sh[d] * t;
    }
}

// ---------------- a_hat[b,v] = sum_d u[b,d]*C3[v,d] ---------------------------
#define GV 128
#define DK 32
__global__ void out_gemm(const float* __restrict__ C3, float* __restrict__ out) {
    __shared__ float Csh[DK][GV + 4];
    __shared__ float Ush[DK][BATCH + 4];

    int tid = threadIdx.x;
    int tx = tid & 15, ty = tid >> 4;
    int v0 = blockIdx.x * GV;

    float acc[8][8];
#pragma unroll
    for (int j = 0; j < 8; ++j)
#pragma unroll
        for (int i = 0; i < 8; ++i) acc[j][i] = 0.0f;

    for (int k0 = 0; k0 < DIM; k0 += DK) {
#pragma unroll
        for (int i = tid; i < DK * GV; i += 256) {
            int kk = i & (DK - 1);
            int vv = i >> 5;
            int v = v0 + vv;
            Csh[kk][vv] = (v < VOCAB) ? __ldg(&C3[(ll)v * DIM + k0 + kk]) : 0.0f;
            Ush[kk][vv] = g_u[vv * DIM + k0 + kk];
        }
        __syncthreads();
#pragma unroll
        for (int kk = 0; kk < DK; ++kk) {
            float a[8], bb[8];
#pragma unroll
            for (int i = 0; i < 8; ++i) a[i]  = Csh[kk][tx * 8 + i];
#pragma unroll
            for (int j = 0; j < 8; ++j) bb[j] = Ush[kk][ty * 8 + j];
#pragma unroll
            for (int j = 0; j < 8; ++j)
#pragma unroll
                for (int i = 0; i < 8; ++i) acc[j][i] = fmaf(a[i], bb[j], acc[j][i]);
        }
        __syncthreads();
    }

#pragma unroll
    for (int j = 0; j < 8; ++j) {
        int b = ty * 8 + j;
#pragma unroll
        for (int i = 0; i < 8; ++i) {
            int v = v0 + tx * 8 + i;
            if (v < VOCAB) out[(ll)b * VOCAB + v] = acc[j][i];
        }
    }
}

// ---------------- launch ------------------------------------------------------
extern "C" void kernel_launch(void* const* d_in, const int* in_sizes, int n_in,
                              void* d_out, int out_size) {
    const void*  story = d_in[0];                 // [B,M,S] int32 or int64
    const void*  query = d_in[1];                 // [B,S]
    const float* C     = (const float*)d_in[2];   // [4,V,D]
    const float* Tw    = (const float*)d_in[3];   // [D,D]
    const float* Tb    = (const float*)d_in[4];   // [D]
    float* out = (float*)d_out;                   // [B,V]

    sniff_kernel<<<1, 256>>>((const int*)story, in_sizes[0]);

    // 4 sequential table passes -> each 25.6MB table stays L2-resident
    float* g_m_ptr;
    cudaGetSymbolAddress((void**)&g_m_ptr, g_m);
    for (int k = 0; k < 4; ++k)
        m_kernel<<<BATCH * MEMSZ, 128>>>(story, C + (ll)k * VOCAB * DIM,
                                         g_m_ptr + (ll)k * BATCH * MEMSZ * DIM);

    u0_kernel<<<BATCH, 128>>>(query, C);

    for (int h = 0; h < HOPS; ++h)
        hop_kernel<<<BATCH, 512>>>(h, Tw, Tb);

    int gv = (VOCAB + GV - 1) / GV;
    out_gemm<<<gv, 256>>>(C + 3ll * VOCAB * DIM, out);
}

// round 6
// speedup vs baseline: 1.8032x; 1.2199x over previous
#include <cuda_runtime.h>
#include <cstdint>

#define BATCH 128
#define MEMSZ 200
#define SENT  50
#define DIM   128
#define VOCAB 50000
#define HOPS  3

typedef long long ll;

// ---------------- scratch (device globals) ------------------------------------
__device__ float g_m[4ll * BATCH * MEMSZ * DIM];   // m_k for tables 0..3
__device__ float g_u[BATCH * DIM];
__device__ int   g_is64;

__device__ __forceinline__ int load_idx(const void* p, ll i, int is64) {
    if (is64) return (int)__ldg(((const ll*)p) + i);
    return __ldg(((const int*)p) + i);
}

// ---------------- dtype sniff -------------------------------------------------
__global__ void sniff_kernel(const int* __restrict__ story32, int n32) {
    __shared__ int any;
    if (threadIdx.x == 0) any = 0;
    __syncthreads();
    int lim = n32 < 20001 ? n32 : 20001;
    int local = 0;
    for (int i = 1 + 2 * (int)threadIdx.x; i < lim; i += 2 * (int)blockDim.x)
        local |= story32[i];
    if (local) atomicOr(&any, 1);
    __syncthreads();
    if (threadIdx.x == 0) g_is64 = (any == 0) ? 1 : 0;
}

// ---------------- m_k[b,m,d] = sum_s C_k[story[b,m,s]][d] * enc(s,d) ----------
// LTS-capped gather. byte offsets precomputed in shared; streaming stores.
__global__ void m_kernel(const void* __restrict__ story, const float* __restrict__ tab,
                         float* __restrict__ mout) {
    int bm   = blockIdx.x;
    int tid  = threadIdx.x;
    int lane = tid & 31, w = tid >> 5;

    __shared__ int    s_off[SENT];          // byte offset into table
    __shared__ float4 part[3][32];

    int is64 = g_is64;
    if (tid < SENT)
        s_off[tid] = load_idx(story, (ll)bm * SENT + tid, is64) * (DIM * 4);
    __syncthreads();

    const int d0 = lane * 4;
    const float cc  = 4.0f / ((float)DIM * (float)SENT);
    const float ed0 = (float)(d0 + 1) - 64.5f;
    const float ed1 = ed0 + 1.0f, ed2 = ed0 + 2.0f, ed3 = ed0 + 3.0f;
    const char* base = (const char*)tab;

    float4 acc = make_float4(0.f, 0.f, 0.f, 0.f);
    for (int s = w; s < SENT; s += 4) {
        float es = (s == SENT - 1) ? 0.0f : ((float)(s + 1) - 25.5f);
        float ce = cc * es;
        float4 v = ((const float4*)(base + s_off[s]))[lane];
        acc.x = fmaf(v.x, fmaf(ce, ed0, 1.0f), acc.x);
        acc.y = fmaf(v.y, fmaf(ce, ed1, 1.0f), acc.y);
        acc.z = fmaf(v.z, fmaf(ce, ed2, 1.0f), acc.z);
        acc.w = fmaf(v.w, fmaf(ce, ed3, 1.0f), acc.w);
    }
    if (w > 0) part[w - 1][lane] = acc;
    __syncthreads();
    if (w == 0) {
        float4 p0 = part[0][lane], p1 = part[1][lane], p2 = part[2][lane];
        acc.x += p0.x + p1.x + p2.x;
        acc.y += p0.y + p1.y + p2.y;
        acc.z += p0.z + p1.z + p2.z;
        acc.w += p0.w + p1.w + p2.w;
        __stcs((float4*)&mout[(ll)bm * DIM + d0], acc);
    }
}

// ---------------- fused u0 + 3 hops: one block per batch element --------------
// 512 threads (16 warps). Dynamic smem: mbuf[200][128] = 100KB ping buffer.
// Hop h: scores from (h==0 ? global m0 : mbuf); prefetch mC rows to registers
// before softmax; o accumulation stashes mC into mbuf for the next hop's scores.
__global__ __launch_bounds__(512, 1)
void hops_kernel(const void* __restrict__ query, const float* __restrict__ C,
                 const float* __restrict__ Tw, const float* __restrict__ Tb) {
    extern __shared__ float mbuf[];          // [MEMSZ][DIM]
    __shared__ float  u_sh[DIM];
    __shared__ float  prob[MEMSZ];
    __shared__ float  red[512];
    __shared__ float4 opart[16][32];
    __shared__ float  o_sh[DIM];
    __shared__ int    qidx[SENT];

    int b    = blockIdx.x;
    int tid  = threadIdx.x;
    int lane = tid & 31, w = tid >> 5;       // 16 warps

    int is64 = g_is64;
    if (tid < SENT) qidx[tid] = load_idx(query, (ll)b * SENT + tid, is64);
    __syncthreads();

    // ---- u0 = position-encoded sum of query embedding ----
    {
        const int d0 = lane * 4;
        const float cc  = 4.0f / ((float)DIM * (float)SENT);
        const float ed0 = (float)(d0 + 1) - 64.5f;
        const float ed1 = ed0 + 1.0f, ed2 = ed0 + 2.0f, ed3 = ed0 + 3.0f;
        float4 acc = make_float4(0.f, 0.f, 0.f, 0.f);
        for (int s = w; s < SENT; s += 16) {
            float es = (s == SENT - 1) ? 0.0f : ((float)(s + 1) - 25.5f);
            float ce = cc * es;
            float4 v = __ldg((const float4*)&C[(ll)qidx[s] * DIM + d0]);
            acc.x = fmaf(v.x, fmaf(ce, ed0, 1.0f), acc.x);
            acc.y = fmaf(v.y, fmaf(ce, ed1, 1.0f), acc.y);
            acc.z = fmaf(v.z, fmaf(ce, ed2, 1.0f), acc.z);
            acc.w = fmaf(v.w, fmaf(ce, ed3, 1.0f), acc.w);
        }
        opart[w][lane] = acc;
        __syncthreads();
        if (tid < 32) {
            float4 s = make_float4(0.f, 0.f, 0.f, 0.f);
#pragma unroll
            for (int ww = 0; ww < 16; ++ww) {
                float4 p = opart[ww][tid];
                s.x += p.x; s.y += p.y; s.z += p.z; s.w += p.w;
            }
            *(float4*)&u_sh[tid * 4] = s;
        }
        __syncthreads();
    }

    const float* m0 = g_m + (ll)b * MEMSZ * DIM;   // table 0 slice of this batch

    for (int h = 0; h < HOPS; ++h) {
        // ---- scores: one warp per memory row ----
        float4 us = *(const float4*)&u_sh[lane * 4];
        for (int m = w; m < MEMSZ; m += 16) {
            float4 v;
            if (h == 0) v = __ldg((const float4*)&m0[(ll)m * DIM + lane * 4]);
            else        v = *(const float4*)&mbuf[m * DIM + lane * 4];
            float s = v.x * us.x + v.y * us.y + v.z * us.z + v.w * us.w;
#pragma unroll
            for (int off = 16; off; off >>= 1) s += __shfl_xor_sync(0xffffffffu, s, off);
            if (lane == 0) prob[m] = s;
        }
        __syncthreads();

        // ---- prefetch mC rows into registers (overlaps the softmax tree) ----
        const float* gC = g_m + ((ll)(h + 1) * BATCH * MEMSZ + (ll)b * MEMSZ) * DIM;
        float4 r[13];
#pragma unroll
        for (int i = 0; i < 13; ++i) {
            int m = w + i * 16;
            if (m < MEMSZ) r[i] = __ldg((const float4*)&gC[(ll)m * DIM + lane * 4]);
        }

        // ---- softmax over MEMSZ ----
        float val = (tid < MEMSZ) ? prob[tid] : -1e30f;
        red[tid] = val; __syncthreads();
#pragma unroll
        for (int s = 256; s > 0; s >>= 1) {
            if (tid < s) red[tid] = fmaxf(red[tid], red[tid + s]);
            __syncthreads();
        }
        float mx = red[0]; __syncthreads();
        float e = (tid < MEMSZ) ? expf(val - mx) : 0.0f;
        red[tid] = e; __syncthreads();
#pragma unroll
        for (int s = 256; s > 0; s >>= 1) {
            if (tid < s) red[tid] += red[tid + s];
            __syncthreads();
        }
        float inv = 1.0f / red[0];
        if (tid < MEMSZ) prob[tid] = e * inv;
        __syncthreads();

        // ---- o accumulation + stash mC into mbuf (becomes next hop's mA) ----
        float4 o = make_float4(0.f, 0.f, 0.f, 0.f);
#pragma unroll
        for (int i = 0; i < 13; ++i) {
            int m = w + i * 16;
            if (m < MEMSZ) {
                float p = prob[m];
                *(float4*)&mbuf[m * DIM + lane * 4] = r[i];
                o.x = fmaf(p, r[i].x, o.x); o.y = fmaf(p, r[i].y, o.y);
                o.z = fmaf(p, r[i].z, o.z); o.w = fmaf(p, r[i].w, o.w);
            }
        }
        opart[w][lane] = o;
        __syncthreads();
        if (tid < 32) {
            float4 s = make_float4(0.f, 0.f, 0.f, 0.f);
#pragma unroll
            for (int ww = 0; ww < 16; ++ww) {
                float4 p = opart[ww][tid];
                s.x += p.x; s.y += p.y; s.z += p.z; s.w += p.w;
            }
            *(float4*)&o_sh[tid * 4] = s;
        }
        __syncthreads();

        // ---- gate: t = sigmoid(Tw[d,:]·u + Tb[d]); 4 threads per d ----
        {
            int d = tid >> 2, q = tid & 3;
            const float* twrow = Tw + (ll)d * DIM + q * 32;
            float part = 0.0f;
#pragma unroll
            for (int j = 0; j < 32; j += 4) {
                float4 tv = __ldg((const float4*)&twrow[j]);
                float4 uv = *(const float4*)&u_sh[q * 32 + j];
                part = fmaf(tv.x, uv.x, part); part = fmaf(tv.y, uv.y, part);
                part = fmaf(tv.z, uv.z, part); part = fmaf(tv.w, uv.w, part);
            }
            red[tid] = part;
        }
        __syncthreads();
        if ((tid & 3) == 0) {
            int d = tid >> 2;
            float t = red[tid] + red[tid + 1] + red[tid + 2] + red[tid + 3] + __ldg(&Tb[d]);
            t = 1.0f / (1.0f + expf(-t));
            float un = (1.0f - t) * u_sh[d] + o_sh[d] * t;
            u_sh[d] = un;
            if (h == HOPS - 1) g_u[b * DIM + d] = un;
        }
        __syncthreads();
    }
}

// ---------------- a_hat[b,v] = sum_d u[b,d]*C3[v,d] ---------------------------
// 128v x 128b tile, 256 threads, 8x8 micro-tile, register-prefetch double buffer.
#define GV 128
#define DK 32
__global__ __launch_bounds__(256, 2)
void out_gemm(const float* __restrict__ C3, float* __restrict__ out) {
    __shared__ float Csh[DK][GV + 4];
    __shared__ float Ush[DK][BATCH + 4];

    int tid = threadIdx.x;
    int tx = tid & 15, ty = tid >> 4;
    int v0 = blockIdx.x * GV;

    float acc[8][8];
#pragma unroll
    for (int j = 0; j < 8; ++j)
#pragma unroll
        for (int i = 0; i < 8; ++i) acc[j][i] = 0.0f;

    float cpre[16], upre[16];

    // prime chunk 0
#pragma unroll
    for (int j = 0; j < 16; ++j) {
        int idx = tid + j * 256;
        int kk = idx & (DK - 1), vv = idx >> 5;
        int v = v0 + vv;
        cpre[j] = (v < VOCAB) ? __ldg(&C3[(ll)v * DIM + kk]) : 0.0f;
        upre[j] = g_u[vv * DIM + kk];
    }
#pragma unroll
    for (int j = 0; j < 16; ++j) {
        int idx = tid + j * 256;
        int kk = idx & (DK - 1), vv = idx >> 5;
        Csh[kk][vv] = cpre[j];
        Ush[kk][vv] = upre[j];
    }

    for (int c = 0; c < DIM / DK; ++c) {
        __syncthreads();
        // prefetch next chunk into registers while computing from shared
        if (c < DIM / DK - 1) {
            int k0 = (c + 1) * DK;
#pragma unroll
            for (int j = 0; j < 16; ++j) {
                int idx = tid + j * 256;
                int kk = idx & (DK - 1), vv = idx >> 5;
                int v = v0 + vv;
                cpre[j] = (v < VOCAB) ? __ldg(&C3[(ll)v * DIM + k0 + kk]) : 0.0f;
                upre[j] = g_u[vv * DIM + k0 + kk];
            }
        }
#pragma unroll
        for (int kk = 0; kk < DK; ++kk) {
            float a[8], bb[8];
#pragma unroll
            for (int i = 0; i < 8; ++i) a[i]  = Csh[kk][tx * 8 + i];
#pragma unroll
            for (int j = 0; j < 8; ++j) bb[j] = Ush[kk][ty * 8 + j];
#pragma unroll
            for (int j = 0; j < 8; ++j)
#pragma unroll
                for (int i = 0; i < 8; ++i) acc[j][i] = fmaf(a[i], bb[j], acc[j][i]);
        }
        __syncthreads();
        if (c < DIM / DK - 1) {
#pragma unroll
            for (int j = 0; j < 16; ++j) {
                int idx = tid + j * 256;
                int kk = idx & (DK - 1), vv = idx >> 5;
                Csh[kk][vv] = cpre[j];
                Ush[kk][vv] = upre[j];
            }
        }
    }

#pragma unroll
    for (int j = 0; j < 8; ++j) {
        int b = ty * 8 + j;
#pragma unroll
        for (int i = 0; i < 8; i += 4) {
            int v = v0 + tx * 8 + i;
            if (v + 3 < VOCAB) {
                float4 st = make_float4(acc[j][i], acc[j][i+1], acc[j][i+2], acc[j][i+3]);
                __stcs((float4*)&out[(ll)b * VOCAB + v], st);
            } else {
                for (int q = 0; q < 4; ++q)
                    if (v + q < VOCAB) out[(ll)b * VOCAB + v + q] = acc[j][i + q];
            }
        }
    }
}

// ---------------- launch ------------------------------------------------------
extern "C" void kernel_launch(void* const* d_in, const int* in_sizes, int n_in,
                              void* d_out, int out_size) {
    const void*  story = d_in[0];                 // [B,M,S] int32 or int64
    const void*  query = d_in[1];                 // [B,S]
    const float* C     = (const float*)d_in[2];   // [4,V,D]
    const float* Tw    = (const float*)d_in[3];   // [D,D]
    const float* Tb    = (const float*)d_in[4];   // [D]
    float* out = (float*)d_out;                   // [B,V]

    // opt-in to 100KB dynamic smem (host-side attr set; no static guards —
    // called unconditionally every invocation, deterministic)
    cudaFuncSetAttribute(hops_kernel, cudaFuncAttributeMaxDynamicSharedMemorySize,
                         MEMSZ * DIM * (int)sizeof(float));

    sniff_kernel<<<1, 256>>>((const int*)story, in_sizes[0]);

    // 4 sequential table passes -> each 25.6MB table stays L2-resident
    float* g_m_ptr;
    cudaGetSymbolAddress((void**)&g_m_ptr, g_m);
    for (int k = 0; k < 4; ++k)
        m_kernel<<<BATCH * MEMSZ, 128>>>(story, C + (ll)k * VOCAB * DIM,
                                         g_m_ptr + (ll)k * BATCH * MEMSZ * DIM);

    // fused u0 + 3 hops (one block per batch element)
    hops_kernel<<<BATCH, 512, MEMSZ * DIM * sizeof(float)>>>(query, C, Tw, Tb);

    // final projection onto vocab
    int gv = (VOCAB + GV - 1) / GV;
    out_gemm<<<gv, 256>>>(C + 3ll * VOCAB * DIM, out);
}

// round 9
// speedup vs baseline: 1.8350x; 1.0176x over previous
#include <cuda_runtime.h>
#include <cuda_fp16.h>
#include <mma.h>
#include <cstdint>

using namespace nvcuda;

#define BATCH 128
#define MEMSZ 200
#define SENT  50
#define DIM   128
#define VOCAB 50000
#define HOPS  3

typedef long long ll;

// ---------------- scratch (device globals) ------------------------------------
__device__ float  g_m[4ll * BATCH * MEMSZ * DIM];    // m_k for tables 0..3 (fp32)
__device__ __half g_C3h[(ll)VOCAB * DIM];            // fp16 copy of table 3
__device__ __half g_uh[BATCH * DIM];                 // final u in fp16
__device__ int    g_is64;

__device__ __forceinline__ int load_idx(const void* p, ll i, int is64) {
    if (is64) return (int)__ldg(((const ll*)p) + i);
    return __ldg(((const int*)p) + i);
}

// ---------------- dtype sniff -------------------------------------------------
__global__ void sniff_kernel(const int* __restrict__ story32, int n32) {
    __shared__ int any;
    if (threadIdx.x == 0) any = 0;
    __syncthreads();
    int lim = n32 < 20001 ? n32 : 20001;
    int local = 0;
    for (int i = 1 + 2 * (int)threadIdx.x; i < lim; i += 2 * (int)blockDim.x)
        local |= story32[i];
    if (local) atomicOr(&any, 1);
    __syncthreads();
    if (threadIdx.x == 0) g_is64 = (any == 0) ? 1 : 0;
}

// ---------------- m_k[b,m,d] = sum_s C_k[story[b,m,s]][d] * enc(s,d) ----------
// fp32 gather — LTS-capped (hardware floor). Streaming output stores.
__global__ void m_kernel(const void* __restrict__ story, const float* __restrict__ tab,
                         float* __restrict__ mout) {
    int bm   = blockIdx.x;
    int tid  = threadIdx.x;
    int lane = tid & 31, w = tid >> 5;

    __shared__ int    s_off[SENT];          // byte offset into table
    __shared__ float4 part[3][32];

    int is64 = g_is64;
    if (tid < SENT)
        s_off[tid] = load_idx(story, (ll)bm * SENT + tid, is64) * (DIM * 4);
    __syncthreads();

    const int d0 = lane * 4;
    const float cc  = 4.0f / ((float)DIM * (float)SENT);
    const float ed0 = (float)(d0 + 1) - 64.5f;
    const float ed1 = ed0 + 1.0f, ed2 = ed0 + 2.0f, ed3 = ed0 + 3.0f;
    const char* base = (const char*)tab;

    float4 acc = make_float4(0.f, 0.f, 0.f, 0.f);
    for (int s = w; s < SENT; s += 4) {
        float es = (s == SENT - 1) ? 0.0f : ((float)(s + 1) - 25.5f);
        float ce = cc * es;
        float4 v = ((const float4*)(base + s_off[s]))[lane];
        acc.x = fmaf(v.x, fmaf(ce, ed0, 1.0f), acc.x);
        acc.y = fmaf(v.y, fmaf(ce, ed1, 1.0f), acc.y);
        acc.z = fmaf(v.z, fmaf(ce, ed2, 1.0f), acc.z);
        acc.w = fmaf(v.w, fmaf(ce, ed3, 1.0f), acc.w);
    }
    if (w > 0) part[w - 1][lane] = acc;
    __syncthreads();
    if (w == 0) {
        float4 p0 = part[0][lane], p1 = part[1][lane], p2 = part[2][lane];
        acc.x += p0.x + p1.x + p2.x;
        acc.y += p0.y + p1.y + p2.y;
        acc.z += p0.z + p1.z + p2.z;
        acc.w += p0.w + p1.w + p2.w;
        __stcs((float4*)&mout[(ll)bm * DIM + d0], acc);
    }
}

// ---------------- table3 fp32 -> fp16 (for wmma output gemm) ------------------
__global__ void conv3h_kernel(const float* __restrict__ C3) {
    ll i = ((ll)blockIdx.x * blockDim.x + threadIdx.x) * 8;
    if (i >= (ll)VOCAB * DIM) return;
    float4 a = __ldg((const float4*)&C3[i]);
    float4 b = __ldg((const float4*)&C3[i + 4]);
    __half2 h0 = __floats2half2_rn(a.x, a.y);
    __half2 h1 = __floats2half2_rn(a.z, a.w);
    __half2 h2 = __floats2half2_rn(b.x, b.y);
    __half2 h3 = __floats2half2_rn(b.z, b.w);
    uint4 st;
    st.x = *(unsigned*)&h0; st.y = *(unsigned*)&h1;
    st.z = *(unsigned*)&h2; st.w = *(unsigned*)&h3;
    __stcg((uint4*)&g_C3h[i], st);
}

// ---------------- fused u0 + 3 hops: one block per batch element --------------
// 512 threads (16 warps). Dynamic smem: mbuf[200][128] = 100KB ping buffer.
__global__ __launch_bounds__(512, 1)
void hops_kernel(const void* __restrict__ query, const float* __restrict__ C,
                 const float* __restrict__ Tw, const float* __restrict__ Tb) {
    extern __shared__ float mbuf[];          // [MEMSZ][DIM]
    __shared__ float  u_sh[DIM];
    __shared__ float  prob[MEMSZ];
    __shared__ float  red[512];
    __shared__ float4 opart[16][32];
    __shared__ float  o_sh[DIM];
    __shared__ int    qidx[SENT];

    int b    = blockIdx.x;
    int tid  = threadIdx.x;
    int lane = tid & 31, w = tid >> 5;       // 16 warps

    int is64 = g_is64;
    if (tid < SENT) qidx[tid] = load_idx(query, (ll)b * SENT + tid, is64);
    __syncthreads();

    // ---- u0 = position-encoded sum of query embedding (fp32 C) ----
    {
        const int d0 = lane * 4;
        const float cc  = 4.0f / ((float)DIM * (float)SENT);
        const float ed0 = (float)(d0 + 1) - 64.5f;
        const float ed1 = ed0 + 1.0f, ed2 = ed0 + 2.0f, ed3 = ed0 + 3.0f;
        float4 acc = make_float4(0.f, 0.f, 0.f, 0.f);
        for (int s = w; s < SENT; s += 16) {
            float es = (s == SENT - 1) ? 0.0f : ((float)(s + 1) - 25.5f);
            float ce = cc * es;
            float4 v = __ldg((const float4*)&C[(ll)qidx[s] * DIM + d0]);
            acc.x = fmaf(v.x, fmaf(ce, ed0, 1.0f), acc.x);
            acc.y = fmaf(v.y, fmaf(ce, ed1, 1.0f), acc.y);
            acc.z = fmaf(v.z, fmaf(ce, ed2, 1.0f), acc.z);
            acc.w = fmaf(v.w, fmaf(ce, ed3, 1.0f), acc.w);
        }
        opart[w][lane] = acc;
        __syncthreads();
        if (tid < 32) {
            float4 s = make_float4(0.f, 0.f, 0.f, 0.f);
#pragma unroll
            for (int ww = 0; ww < 16; ++ww) {
                float4 p = opart[ww][tid];
                s.x += p.x; s.y += p.y; s.z += p.z; s.w += p.w;
            }
            *(float4*)&u_sh[tid * 4] = s;
        }
        __syncthreads();
    }

    const float* m0 = g_m + (ll)b * MEMSZ * DIM;   // table 0 slice of this batch

    for (int h = 0; h < HOPS; ++h) {
        // ---- scores: one warp per memory row ----
        float4 us = *(const float4*)&u_sh[lane * 4];
        for (int m = w; m < MEMSZ; m += 16) {
            float4 v;
            if (h == 0) v = __ldg((const float4*)&m0[(ll)m * DIM + lane * 4]);
            else        v = *(const float4*)&mbuf[m * DIM + lane * 4];
            float s = v.x * us.x + v.y * us.y + v.z * us.z + v.w * us.w;
#pragma unroll
            for (int off = 16; off; off >>= 1) s += __shfl_xor_sync(0xffffffffu, s, off);
            if (lane == 0) prob[m] = s;
        }
        __syncthreads();

        // ---- prefetch mC rows into registers (overlaps the softmax) ----
        const float* gC = g_m + ((ll)(h + 1) * BATCH * MEMSZ + (ll)b * MEMSZ) * DIM;
        float4 r[13];
#pragma unroll
        for (int i = 0; i < 13; ++i) {
            int m = w + i * 16;
            if (m < MEMSZ) r[i] = __ldg((const float4*)&gC[(ll)m * DIM + lane * 4]);
        }

        // ---- softmax over MEMSZ: single-warp shuffle reduction (2 barriers) ----
        if (tid < 32) {
            float v[7];
            float mx = -1e30f;
#pragma unroll
            for (int j = 0; j < 7; ++j) {
                int m = tid + j * 32;
                v[j] = (m < MEMSZ) ? prob[m] : -1e30f;
                mx = fmaxf(mx, v[j]);
            }
#pragma unroll
            for (int off = 16; off; off >>= 1)
                mx = fmaxf(mx, __shfl_xor_sync(0xffffffffu, mx, off));
            float sum = 0.0f;
#pragma unroll
            for (int j = 0; j < 7; ++j) { v[j] = expf(v[j] - mx); sum += v[j]; }
#pragma unroll
            for (int off = 16; off; off >>= 1)
                sum += __shfl_xor_sync(0xffffffffu, sum, off);
            float inv = 1.0f / sum;
#pragma unroll
            for (int j = 0; j < 7; ++j) {
                int m = tid + j * 32;
                if (m < MEMSZ) prob[m] = v[j] * inv;
            }
        }
        __syncthreads();

        // ---- o accumulation + stash mC into mbuf (becomes next hop's mA) ----
        float4 o = make_float4(0.f, 0.f, 0.f, 0.f);
#pragma unroll
        for (int i = 0; i < 13; ++i) {
            int m = w + i * 16;
            if (m < MEMSZ) {
                float p = prob[m];
                *(float4*)&mbuf[m * DIM + lane * 4] = r[i];
                o.x = fmaf(p, r[i].x, o.x); o.y = fmaf(p, r[i].y, o.y);
                o.z = fmaf(p, r[i].z, o.z); o.w = fmaf(p, r[i].w, o.w);
            }
        }
        opart[w][lane] = o;
        __syncthreads();
        if (tid < 32) {
            float4 s = make_float4(0.f, 0.f, 0.f, 0.f);
#pragma unroll
            for (int ww = 0; ww < 16; ++ww) {
                float4 p = opart[ww][tid];
                s.x += p.x; s.y += p.y; s.z += p.z; s.w += p.w;
            }
            *(float4*)&o_sh[tid * 4] = s;
        }
        __syncthreads();

        // ---- gate: t = sigmoid(Tw[d,:]·u + Tb[d]); 4 threads per d ----
        {
            int d = tid >> 2, q = tid & 3;
            const float* twrow = Tw + (ll)d * DIM + q * 32;
            float part = 0.0f;
#pragma unroll
            for (int j = 0; j < 32; j += 4) {
                float4 tv = __ldg((const float4*)&twrow[j]);
                float4 uv = *(const float4*)&u_sh[q * 32 + j];
                part = fmaf(tv.x, uv.x, part); part = fmaf(tv.y, uv.y, part);
                part = fmaf(tv.z, uv.z, part); part = fmaf(tv.w, uv.w, part);
            }
            red[tid] = part;
        }
        __syncthreads();
        if ((tid & 3) == 0) {
            int d = tid >> 2;
            float t = red[tid] + red[tid + 1] + red[tid + 2] + red[tid + 3] + __ldg(&Tb[d]);
            t = 1.0f / (1.0f + expf(-t));
            float un = (1.0f - t) * u_sh[d] + o_sh[d] * t;
            u_sh[d] = un;
            if (h == HOPS - 1) g_uh[b * DIM + d] = __float2half(un);
        }
        __syncthreads();
    }
}

// ---------------- a_hat[b,v] = sum_d u[b,d]*C3[v,d] via wmma fp16 -------------
// block = 256 thr (8 warps), tile 128v x 128b x 128k. dyn smem 64KB.
// warp w owns rows [w*16, w*16+16); 8 acc frags cover all 128 b columns.
__global__ __launch_bounds__(256, 2)
void out_gemm(float* __restrict__ out) {
    extern __shared__ __half sh[];
    __half* As = sh;                 // C3h tile [128][128]
    __half* Bs = sh + 128 * 128;     // uh       [128][128]

    int tid = threadIdx.x;
    int wid = tid >> 5;
    int v0  = blockIdx.x * 128;

    // load A tile (skip OOB rows; their accs are never stored)
    for (int i = tid; i < 128 * 16; i += 256) {
        int row = i >> 4, seg = i & 15;
        if (v0 + row < VOCAB)
            ((uint4*)As)[i] = __ldg(((const uint4*)(g_C3h + (ll)(v0 + row) * DIM)) + seg);
    }
    // load full u (fp16) once
    for (int i = tid; i < 128 * 16; i += 256)
        ((uint4*)Bs)[i] = __ldg(((const uint4*)g_uh) + i);
    __syncthreads();

    wmma::fragment<wmma::accumulator, 16, 16, 16, float> acc[8];
#pragma unroll
    for (int n = 0; n < 8; ++n) wmma::fill_fragment(acc[n], 0.0f);

#pragma unroll
    for (int kt = 0; kt < 8; ++kt) {
        wmma::fragment<wmma::matrix_a, 16, 16, 16, __half, wmma::row_major> af;
        wmma::load_matrix_sync(af, As + (wid * 16) * 128 + kt * 16, 128);
#pragma unroll
        for (int n = 0; n < 8; ++n) {
            wmma::fragment<wmma::matrix_b, 16, 16, 16, __half, wmma::col_major> bf;
            wmma::load_matrix_sync(bf, Bs + (n * 16) * 128 + kt * 16, 128);
            wmma::mma_sync(acc[n], af, bf, acc[n]);
        }
    }

    // store: out[b][v]; frag (m=v_local, n=b_local) -> col_major with ldm=VOCAB
    if (v0 + wid * 16 + 16 <= VOCAB) {
#pragma unroll
        for (int n = 0; n < 8; ++n)
            wmma::store_matrix_sync(out + (ll)(n * 16) * VOCAB + v0 + wid * 16,
                                    acc[n], VOCAB, wmma::mem_col_major);
    }
}

// ---------------- launch ------------------------------------------------------
extern "C" void kernel_launch(void* const* d_in, const int* in_sizes, int n_in,
                              void* d_out, int out_size) {
    const void*  story = d_in[0];                 // [B,M,S] int32 or int64
    const void*  query = d_in[1];                 // [B,S]
    const float* C     = (const float*)d_in[2];   // [4,V,D]
    const float* Tw    = (const float*)d_in[3];   // [D,D]
    const float* Tb    = (const float*)d_in[4];   // [D]
    float* out = (float*)d_out;                   // [B,V]

    cudaFuncSetAttribute(hops_kernel, cudaFuncAttributeMaxDynamicSharedMemorySize,
                         MEMSZ * DIM * (int)sizeof(float));
    cudaFuncSetAttribute(out_gemm, cudaFuncAttributeMaxDynamicSharedMemorySize,
                         2 * 128 * 128 * (int)sizeof(__half));

    sniff_kernel<<<1, 256>>>((const int*)story, in_sizes[0]);

    // 4 sequential fp32 table passes (each 25.6MB table L2-resident)
    float* g_m_ptr;
    cudaGetSymbolAddress((void**)&g_m_ptr, g_m);
    for (int k = 0; k < 4; ++k)
        m_kernel<<<BATCH * MEMSZ, 128>>>(story, C + (ll)k * VOCAB * DIM,
                                         g_m_ptr + (ll)k * BATCH * MEMSZ * DIM);

    // table3 -> fp16 (L2 still warm from the table-3 gather)
    {
        ll n8 = ((ll)VOCAB * DIM) / 8;
        conv3h_kernel<<<(int)((n8 + 255) / 256), 256>>>(C + 3ll * VOCAB * DIM);
    }

    // fused u0 + 3 hops (writes g_uh)
    hops_kernel<<<BATCH, 512, MEMSZ * DIM * sizeof(float)>>>(query, C, Tw, Tb);

    // final projection via tensor cores (fp16 in, fp32 accum)
    out_gemm<<<(VOCAB + 127) / 128, 256, 2 * 128 * 128 * sizeof(__half)>>>(out);
}

// round 10
// speedup vs baseline: 1.8635x; 1.0155x over previous
#include <cuda_runtime.h>
#include <cuda_fp16.h>
#include <mma.h>
#include <cstdint>

using namespace nvcuda;

#define BATCH 128
#define MEMSZ 200
#define SENT  50
#define DIM   128
#define VOCAB 50000
#define HOPS  3

typedef long long ll;

// ---------------- scratch (device globals) ------------------------------------
__device__ float  g_m[4ll * BATCH * MEMSZ * DIM];    // m_k for tables 0..3 (fp32)
__device__ __half g_uh[BATCH * DIM];                 // final u in fp16
__device__ int    g_is64;

__device__ __forceinline__ int load_idx(const void* p, ll i, int is64) {
    if (is64) return (int)__ldg(((const ll*)p) + i);
    return __ldg(((const int*)p) + i);
}

// ---------------- dtype sniff -------------------------------------------------
__global__ void sniff_kernel(const int* __restrict__ story32, int n32) {
    __shared__ int any;
    if (threadIdx.x == 0) any = 0;
    __syncthreads();
    int lim = n32 < 20001 ? n32 : 20001;
    int local = 0;
    for (int i = 1 + 2 * (int)threadIdx.x; i < lim; i += 2 * (int)blockDim.x)
        local |= story32[i];
    if (local) atomicOr(&any, 1);
    __syncthreads();
    if (threadIdx.x == 0) g_is64 = (any == 0) ? 1 : 0;
}

// ---------------- m_k[b,m,d] = sum_s C_k[story[b,m,s]][d] * enc(s,d) ----------
// fp32 gather — LTS-capped (hardware floor). Plain stores keep g_m L2-resident
// for the hops kernel's reads.
__global__ void m_kernel(const void* __restrict__ story, const float* __restrict__ tab,
                         float* __restrict__ mout) {
    int bm   = blockIdx.x;
    int tid  = threadIdx.x;
    int lane = tid & 31, w = tid >> 5;

    __shared__ int    s_off[SENT];          // byte offset into table
    __shared__ float4 part[3][32];

    int is64 = g_is64;
    if (tid < SENT)
        s_off[tid] = load_idx(story, (ll)bm * SENT + tid, is64) * (DIM * 4);
    __syncthreads();

    const int d0 = lane * 4;
    const float cc  = 4.0f / ((float)DIM * (float)SENT);
    const float ed0 = (float)(d0 + 1) - 64.5f;
    const float ed1 = ed0 + 1.0f, ed2 = ed0 + 2.0f, ed3 = ed0 + 3.0f;
    const char* base = (const char*)tab;

    float4 acc = make_float4(0.f, 0.f, 0.f, 0.f);
    for (int s = w; s < SENT; s += 4) {
        float es = (s == SENT - 1) ? 0.0f : ((float)(s + 1) - 25.5f);
        float ce = cc * es;
        float4 v = ((const float4*)(base + s_off[s]))[lane];
        acc.x = fmaf(v.x, fmaf(ce, ed0, 1.0f), acc.x);
        acc.y = fmaf(v.y, fmaf(ce, ed1, 1.0f), acc.y);
        acc.z = fmaf(v.z, fmaf(ce, ed2, 1.0f), acc.z);
        acc.w = fmaf(v.w, fmaf(ce, ed3, 1.0f), acc.w);
    }
    if (w > 0) part[w - 1][lane] = acc;
    __syncthreads();
    if (w == 0) {
        float4 p0 = part[0][lane], p1 = part[1][lane], p2 = part[2][lane];
        acc.x += p0.x + p1.x + p2.x;
        acc.y += p0.y + p1.y + p2.y;
        acc.z += p0.z + p1.z + p2.z;
        acc.w += p0.w + p1.w + p2.w;
        *(float4*)&mout[(ll)bm * DIM + d0] = acc;   // cached: hops re-reads from L2
    }
}

// ---------------- fused u0 + 3 hops: one block per batch element --------------
// 512 threads (16 warps). Dynamic smem: mbuf[200][128] = 100KB ping buffer.
__global__ __launch_bounds__(512, 1)
void hops_kernel(const void* __restrict__ query, const float* __restrict__ C,
                 const float* __restrict__ Tw, const float* __restrict__ Tb) {
    extern __shared__ float mbuf[];          // [MEMSZ][DIM]
    __shared__ float  u_sh[DIM];
    __shared__ float  prob[MEMSZ];
    __shared__ float  red[512];
    __shared__ float4 opart[16][32];
    __shared__ float  o_sh[DIM];
    __shared__ int    qidx[SENT];

    int b    = blockIdx.x;
    int tid  = threadIdx.x;
    int lane = tid & 31, w = tid >> 5;       // 16 warps

    int is64 = g_is64;
    if (tid < SENT) qidx[tid] = load_idx(query, (ll)b * SENT + tid, is64);
    __syncthreads();

    // ---- u0 = position-encoded sum of query embedding (fp32 C) ----
    {
        const int d0 = lane * 4;
        const float cc  = 4.0f / ((float)DIM * (float)SENT);
        const float ed0 = (float)(d0 + 1) - 64.5f;
        const float ed1 = ed0 + 1.0f, ed2 = ed0 + 2.0f, ed3 = ed0 + 3.0f;
        float4 acc = make_float4(0.f, 0.f, 0.f, 0.f);
        for (int s = w; s < SENT; s += 16) {
            float es = (s == SENT - 1) ? 0.0f : ((float)(s + 1) - 25.5f);
            float ce = cc * es;
            float4 v = __ldg((const float4*)&C[(ll)qidx[s] * DIM + d0]);
            acc.x = fmaf(v.x, fmaf(ce, ed0, 1.0f), acc.x);
            acc.y = fmaf(v.y, fmaf(ce, ed1, 1.0f), acc.y);
            acc.z = fmaf(v.z, fmaf(ce, ed2, 1.0f), acc.z);
            acc.w = fmaf(v.w, fmaf(ce, ed3, 1.0f), acc.w);
        }
        opart[w][lane] = acc;
        __syncthreads();
        if (tid < 32) {
            float4 s = make_float4(0.f, 0.f, 0.f, 0.f);
#pragma unroll
            for (int ww = 0; ww < 16; ++ww) {
                float4 p = opart[ww][tid];
                s.x += p.x; s.y += p.y; s.z += p.z; s.w += p.w;
            }
            *(float4*)&u_sh[tid * 4] = s;
        }
        __syncthreads();
    }

    const float* m0 = g_m + (ll)b * MEMSZ * DIM;   // table 0 slice of this batch

    for (int h = 0; h < HOPS; ++h) {
        // ---- scores: one warp per memory row ----
        float4 us = *(const float4*)&u_sh[lane * 4];
        for (int m = w; m < MEMSZ; m += 16) {
            float4 v;
            if (h == 0) v = __ldg((const float4*)&m0[(ll)m * DIM + lane * 4]);
            else        v = *(const float4*)&mbuf[m * DIM + lane * 4];
            float s = v.x * us.x + v.y * us.y + v.z * us.z + v.w * us.w;
#pragma unroll
            for (int off = 16; off; off >>= 1) s += __shfl_xor_sync(0xffffffffu, s, off);
            if (lane == 0) prob[m] = s;
        }
        __syncthreads();

        // ---- prefetch mC rows into registers (overlaps the softmax) ----
        const float* gC = g_m + ((ll)(h + 1) * BATCH * MEMSZ + (ll)b * MEMSZ) * DIM;
        float4 r[13];
#pragma unroll
        for (int i = 0; i < 13; ++i) {
            int m = w + i * 16;
            if (m < MEMSZ) r[i] = __ldg((const float4*)&gC[(ll)m * DIM + lane * 4]);
        }

        // ---- softmax over MEMSZ: single-warp shuffle reduction ----
        if (tid < 32) {
            float v[7];
            float mx = -1e30f;
#pragma unroll
            for (int j = 0; j < 7; ++j) {
                int m = tid + j * 32;
                v[j] = (m < MEMSZ) ? prob[m] : -1e30f;
                mx = fmaxf(mx, v[j]);
            }
#pragma unroll
            for (int off = 16; off; off >>= 1)
                mx = fmaxf(mx, __shfl_xor_sync(0xffffffffu, mx, off));
            float sum = 0.0f;
#pragma unroll
            for (int j = 0; j < 7; ++j) { v[j] = expf(v[j] - mx); sum += v[j]; }
#pragma unroll
            for (int off = 16; off; off >>= 1)
                sum += __shfl_xor_sync(0xffffffffu, sum, off);
            float inv = 1.0f / sum;
#pragma unroll
            for (int j = 0; j < 7; ++j) {
                int m = tid + j * 32;
                if (m < MEMSZ) prob[m] = v[j] * inv;
            }
        }
        __syncthreads();

        // ---- o accumulation + stash mC into mbuf (becomes next hop's mA) ----
        float4 o = make_float4(0.f, 0.f, 0.f, 0.f);
#pragma unroll
        for (int i = 0; i < 13; ++i) {
            int m = w + i * 16;
            if (m < MEMSZ) {
                float p = prob[m];
                *(float4*)&mbuf[m * DIM + lane * 4] = r[i];
                o.x = fmaf(p, r[i].x, o.x); o.y = fmaf(p, r[i].y, o.y);
                o.z = fmaf(p, r[i].z, o.z); o.w = fmaf(p, r[i].w, o.w);
            }
        }
        opart[w][lane] = o;
        __syncthreads();
        if (tid < 32) {
            float4 s = make_float4(0.f, 0.f, 0.f, 0.f);
#pragma unroll
            for (int ww = 0; ww < 16; ++ww) {
                float4 p = opart[ww][tid];
                s.x += p.x; s.y += p.y; s.z += p.z; s.w += p.w;
            }
            *(float4*)&o_sh[tid * 4] = s;
        }
        __syncthreads();

        // ---- gate: t = sigmoid(Tw[d,:]·u + Tb[d]); 4 threads per d ----
        {
            int d = tid >> 2, q = tid & 3;
            const float* twrow = Tw + (ll)d * DIM + q * 32;
            float part = 0.0f;
#pragma unroll
            for (int j = 0; j < 32; j += 4) {
                float4 tv = __ldg((const float4*)&twrow[j]);
                float4 uv = *(const float4*)&u_sh[q * 32 + j];
                part = fmaf(tv.x, uv.x, part); part = fmaf(tv.y, uv.y, part);
                part = fmaf(tv.z, uv.z, part); part = fmaf(tv.w, uv.w, part);
            }
            red[tid] = part;
        }
        __syncthreads();
        if ((tid & 3) == 0) {
            int d = tid >> 2;
            float t = red[tid] + red[tid + 1] + red[tid + 2] + red[tid + 3] + __ldg(&Tb[d]);
            t = 1.0f / (1.0f + expf(-t));
            float un = (1.0f - t) * u_sh[d] + o_sh[d] * t;
            u_sh[d] = un;
            if (h == HOPS - 1) g_uh[b * DIM + d] = __float2half(un);
        }
        __syncthreads();
    }
}

// ---------------- a_hat[b,v] = sum_d u[b,d]*C3[v,d] via wmma fp16 -------------
// Loads C3 in fp32, converts to fp16 in registers while staging to smem
// (eliminates the separate conversion kernel). block = 256 thr (8 warps),
// tile 128v x 128b x 128k, dyn smem 64KB.
__global__ __launch_bounds__(256, 2)
void out_gemm(const float* __restrict__ C3, float* __restrict__ out) {
    extern __shared__ __half sh[];
    __half* As = sh;                 // C3 tile as fp16 [128][128]
    __half* Bs = sh + 128 * 128;     // uh            [128][128]

    int tid = threadIdx.x;
    int wid = tid >> 5;
    int v0  = blockIdx.x * 128;

    // load A tile fp32 -> convert -> fp16 smem (128 rows x 32 float4 each)
    for (int i = tid; i < 128 * 32; i += 256) {
        int row = i >> 5, seg = i & 31;
        if (v0 + row < VOCAB) {
            float4 f = __ldg((const float4*)&C3[(ll)(v0 + row) * DIM + seg * 4]);
            __half2 h0 = __floats2half2_rn(f.x, f.y);
            __half2 h1 = __floats2half2_rn(f.z, f.w);
            uint2 st;
            st.x = *(unsigned*)&h0; st.y = *(unsigned*)&h1;
            *(uint2*)&As[row * 128 + seg * 4] = st;
        }
    }
    // load full u (fp16) once
    for (int i = tid; i < 128 * 16; i += 256)
        ((uint4*)Bs)[i] = __ldg(((const uint4*)g_uh) + i);
    __syncthreads();

    wmma::fragment<wmma::accumulator, 16, 16, 16, float> acc[8];
#pragma unroll
    for (int n = 0; n < 8; ++n) wmma::fill_fragment(acc[n], 0.0f);

#pragma unroll
    for (int kt = 0; kt < 8; ++kt) {
        wmma::fragment<wmma::matrix_a, 16, 16, 16, __half, wmma::row_major> af;
        wmma::load_matrix_sync(af, As + (wid * 16) * 128 + kt * 16, 128);
#pragma unroll
        for (int n = 0; n < 8; ++n) {
            wmma::fragment<wmma::matrix_b, 16, 16, 16, __half, wmma::col_major> bf;
            wmma::load_matrix_sync(bf, Bs + (n * 16) * 128 + kt * 16, 128);
            wmma::mma_sync(acc[n], af, bf, acc[n]);
        }
    }

    // store: out[b][v]; frag (m=v_local, n=b_local) -> col_major with ldm=VOCAB
    if (v0 + wid * 16 + 16 <= VOCAB) {
#pragma unroll
        for (int n = 0; n < 8; ++n)
            wmma::store_matrix_sync(out + (ll)(n * 16) * VOCAB + v0 + wid * 16,
                                    acc[n], VOCAB, wmma::mem_col_major);
    }
}

// ---------------- launch ------------------------------------------------------
extern "C" void kernel_launch(void* const* d_in, const int* in_sizes, int n_in,
                              void* d_out, int out_size) {
    const void*  story = d_in[0];                 // [B,M,S] int32 or int64
    const void*  query = d_in[1];                 // [B,S]
    const float* C     = (const float*)d_in[2];   // [4,V,D]
    const float* Tw    = (const float*)d_in[3];   // [D,D]
    const float* Tb    = (const float*)d_in[4];   // [D]
    float* out = (float*)d_out;                   // [B,V]

    cudaFuncSetAttribute(hops_kernel, cudaFuncAttributeMaxDynamicSharedMemorySize,
                         MEMSZ * DIM * (int)sizeof(float));
    cudaFuncSetAttribute(out_gemm, cudaFuncAttributeMaxDynamicSharedMemorySize,
                         2 * 128 * 128 * (int)sizeof(__half));

    sniff_kernel<<<1, 256>>>((const int*)story, in_sizes[0]);

    // 4 sequential fp32 table passes (each 25.6MB table L2-resident)
    float* g_m_ptr;
    cudaGetSymbolAddress((void**)&g_m_ptr, g_m);
    for (int k = 0; k < 4; ++k)
        m_kernel<<<BATCH * MEMSZ, 128>>>(story, C + (ll)k * VOCAB * DIM,
                                         g_m_ptr + (ll)k * BATCH * MEMSZ * DIM);

    // fused u0 + 3 hops (writes g_uh)
    hops_kernel<<<BATCH, 512, MEMSZ * DIM * sizeof(float)>>>(query, C, Tw, Tb);

    // final projection via tensor cores (fp32 C3 converted in-kernel)
    out_gemm<<<(VOCAB + 127) / 128, 256, 2 * 128 * 128 * sizeof(__half)>>>(
        C + 3ll * VOCAB * DIM, out);
}

// round 12
// speedup vs baseline: 1.8777x; 1.0076x over previous
#include <cuda_runtime.h>
#include <cuda_fp16.h>
#include <mma.h>
#include <cstdint>

using namespace nvcuda;

#define BATCH 128
#define MEMSZ 200
#define SENT  50
#define DIM   128
#define VOCAB 50000
#define HOPS  3

typedef long long ll;

// ---------------- scratch (device globals) ------------------------------------
__device__ float  g_m[4ll * BATCH * MEMSZ * DIM];    // m_k for tables 0..3 (fp32)
__device__ float  g_u[BATCH * DIM];                  // u between hops (fp32)
__device__ __half g_uh[BATCH * DIM];                 // final u in fp16
__device__ int    g_is64;

__device__ __forceinline__ int load_idx(const void* p, ll i, int is64) {
    if (is64) return (int)__ldg(((const ll*)p) + i);
    return __ldg(((const int*)p) + i);
}

// ---------------- dtype sniff -------------------------------------------------
__global__ void sniff_kernel(const int* __restrict__ story32, int n32) {
    __shared__ int any;
    if (threadIdx.x == 0) any = 0;
    __syncthreads();
    int lim = n32 < 20001 ? n32 : 20001;
    int local = 0;
    for (int i = 1 + 2 * (int)threadIdx.x; i < lim; i += 2 * (int)blockDim.x)
        local |= story32[i];
    if (local) atomicOr(&any, 1);
    __syncthreads();
    if (threadIdx.x == 0) g_is64 = (any == 0) ? 1 : 0;
}

// ---------------- m_k[b,m,d] = sum_s C_k[story[b,m,s]][d] * enc(s,d) ----------
// fp32 gather — LTS-capped (hardware floor).
__global__ void m_kernel(const void* __restrict__ story, const float* __restrict__ tab,
                         float* __restrict__ mout) {
    int bm   = blockIdx.x;
    int tid  = threadIdx.x;
    int lane = tid & 31, w = tid >> 5;

    __shared__ int    s_off[SENT];          // byte offset into table
    __shared__ float4 part[3][32];

    int is64 = g_is64;
    if (tid < SENT)
        s_off[tid] = load_idx(story, (ll)bm * SENT + tid, is64) * (DIM * 4);
    __syncthreads();

    const int d0 = lane * 4;
    const float cc  = 4.0f / ((float)DIM * (float)SENT);
    const float ed0 = (float)(d0 + 1) - 64.5f;
    const float ed1 = ed0 + 1.0f, ed2 = ed0 + 2.0f, ed3 = ed0 + 3.0f;
    const char* base = (const char*)tab;

    float4 acc = make_float4(0.f, 0.f, 0.f, 0.f);
    for (int s = w; s < SENT; s += 4) {
        float es = (s == SENT - 1) ? 0.0f : ((float)(s + 1) - 25.5f);
        float ce = cc * es;
        float4 v = ((const float4*)(base + s_off[s]))[lane];
        acc.x = fmaf(v.x, fmaf(ce, ed0, 1.0f), acc.x);
        acc.y = fmaf(v.y, fmaf(ce, ed1, 1.0f), acc.y);
        acc.z = fmaf(v.z, fmaf(ce, ed2, 1.0f), acc.z);
        acc.w = fmaf(v.w, fmaf(ce, ed3, 1.0f), acc.w);
    }
    if (w > 0) part[w - 1][lane] = acc;
    __syncthreads();
    if (w == 0) {
        float4 p0 = part[0][lane], p1 = part[1][lane], p2 = part[2][lane];
        acc.x += p0.x + p1.x + p2.x;
        acc.y += p0.y + p1.y + p2.y;
        acc.z += p0.z + p1.z + p2.z;
        acc.w += p0.w + p1.w + p2.w;
        *(float4*)&mout[(ll)bm * DIM + d0] = acc;
    }
}

// ---------------- u0[b,d] = sum_s C0[query[b,s]][d] * enc(s,d) ---------------
__global__ void u0_kernel(const void* __restrict__ query, const float* __restrict__ C) {
    int b    = blockIdx.x;
    int tid  = threadIdx.x;
    int lane = tid & 31, w = tid >> 5;

    __shared__ int    s_idx[SENT];
    __shared__ float4 part[3][32];

    int is64 = g_is64;
    if (tid < SENT) s_idx[tid] = load_idx(query, (ll)b * SENT + tid, is64);
    __syncthreads();

    const int d0 = lane * 4;
    const float cc  = 4.0f / ((float)DIM * (float)SENT);
    const float ed0 = (float)(d0 + 1) - 64.5f;
    const float ed1 = ed0 + 1.0f, ed2 = ed0 + 2.0f, ed3 = ed0 + 3.0f;

    float4 acc = make_float4(0.f, 0.f, 0.f, 0.f);
    for (int s = w; s < SENT; s += 4) {
        float es = (s == SENT - 1) ? 0.0f : ((float)(s + 1) - 25.5f);
        float ce = cc * es;
        float4 v = __ldg((const float4*)&C[(ll)s_idx[s] * DIM + d0]);
        acc.x = fmaf(v.x, fmaf(ce, ed0, 1.0f), acc.x);
        acc.y = fmaf(v.y, fmaf(ce, ed1, 1.0f), acc.y);
        acc.z = fmaf(v.z, fmaf(ce, ed2, 1.0f), acc.z);
        acc.w = fmaf(v.w, fmaf(ce, ed3, 1.0f), acc.w);
    }
    if (w > 0) part[w - 1][lane] = acc;
    __syncthreads();
    if (w == 0) {
        float4 p0 = part[0][lane], p1 = part[1][lane], p2 = part[2][lane];
        acc.x += p0.x + p1.x + p2.x;
        acc.y += p0.y + p1.y + p2.y;
        acc.z += p0.z + p1.z + p2.z;
        acc.w += p0.w + p1.w + p2.w;
        *(float4*)&g_u[b * DIM + d0] = acc;
    }
}

// ---------------- one hop (standalone; overlaps the gather stream) ------------
// 512 threads (16 warps). mA = g_m[h], mC = g_m[h+1]; u carried in g_u.
__global__ __launch_bounds__(512, 1)
void hop_kernel(int h, const float* __restrict__ Tw, const float* __restrict__ Tb) {
    __shared__ float  u_sh[DIM];
    __shared__ float  prob[MEMSZ];
    __shared__ float  red[512];
    __shared__ float4 opart[16][32];
    __shared__ float  o_sh[DIM];

    int b    = blockIdx.x;
    int tid  = threadIdx.x;
    int lane = tid & 31, w = tid >> 5;       // 16 warps

    if (tid < DIM) u_sh[tid] = g_u[b * DIM + tid];
    __syncthreads();

    const float* mA = g_m + ((ll)h * BATCH * MEMSZ + (ll)b * MEMSZ) * DIM;
    const float* mC = mA + (ll)BATCH * MEMSZ * DIM;

    // ---- scores: one warp per memory row ----
    float4 us = *(const float4*)&u_sh[lane * 4];
    for (int m = w; m < MEMSZ; m += 16) {
        float4 v = __ldg((const float4*)&mA[(ll)m * DIM + lane * 4]);
        float s = v.x * us.x + v.y * us.y + v.z * us.z + v.w * us.w;
#pragma unroll
        for (int off = 16; off; off >>= 1) s += __shfl_xor_sync(0xffffffffu, s, off);
        if (lane == 0) prob[m] = s;
    }
    __syncthreads();

    // ---- prefetch mC rows into registers (overlaps the softmax) ----
    float4 r[13];
#pragma unroll
    for (int i = 0; i < 13; ++i) {
        int m = w + i * 16;
        if (m < MEMSZ) r[i] = __ldg((const float4*)&mC[(ll)m * DIM + lane * 4]);
    }

    // ---- softmax over MEMSZ: single-warp shuffle reduction ----
    if (tid < 32) {
        float v[7];
        float mx = -1e30f;
#pragma unroll
        for (int j = 0; j < 7; ++j) {
            int m = tid + j * 32;
            v[j] = (m < MEMSZ) ? prob[m] : -1e30f;
            mx = fmaxf(mx, v[j]);
        }
#pragma unroll
        for (int off = 16; off; off >>= 1)
            mx = fmaxf(mx, __shfl_xor_sync(0xffffffffu, mx, off));
        float sum = 0.0f;
#pragma unroll
        for (int j = 0; j < 7; ++j) { v[j] = expf(v[j] - mx); sum += v[j]; }
#pragma unroll
        for (int off = 16; off; off >>= 1)
            sum += __shfl_xor_sync(0xffffffffu, sum, off);
        float inv = 1.0f / sum;
#pragma unroll
        for (int j = 0; j < 7; ++j) {
            int m = tid + j * 32;
            if (m < MEMSZ) prob[m] = v[j] * inv;
        }
    }
    __syncthreads();

    // ---- o[d] = sum_m prob[m]*mC[m][d]: warp-partitioned over m ----
    float4 o = make_float4(0.f, 0.f, 0.f, 0.f);
#pragma unroll
    for (int i = 0; i < 13; ++i) {
        int m = w + i * 16;
        if (m < MEMSZ) {
            float p = prob[m];
            o.x = fmaf(p, r[i].x, o.x); o.y = fmaf(p, r[i].y, o.y);
            o.z = fmaf(p, r[i].z, o.z); o.w = fmaf(p, r[i].w, o.w);
        }
    }
    opart[w][lane] = o;
    __syncthreads();
    if (tid < 32) {
        float4 s = make_float4(0.f, 0.f, 0.f, 0.f);
#pragma unroll
        for (int ww = 0; ww < 16; ++ww) {
            float4 p = opart[ww][tid];
            s.x += p.x; s.y += p.y; s.z += p.z; s.w += p.w;
        }
        *(float4*)&o_sh[tid * 4] = s;
    }
    __syncthreads();

    // ---- gate: t = sigmoid(Tw[d,:]·u + Tb[d]); 4 threads per d ----
    {
        int d = tid >> 2, q = tid & 3;
        const float* twrow = Tw + (ll)d * DIM + q * 32;
        float part = 0.0f;
#pragma unroll
        for (int j = 0; j < 32; j += 4) {
            float4 tv = __ldg((const float4*)&twrow[j]);
            float4 uv = *(const float4*)&u_sh[q * 32 + j];
            part = fmaf(tv.x, uv.x, part); part = fmaf(tv.y, uv.y, part);
            part = fmaf(tv.z, uv.z, part); part = fmaf(tv.w, uv.w, part);
        }
        red[tid] = part;
    }
    __syncthreads();
    if ((tid & 3) == 0) {
        int d = tid >> 2;
        float t = red[tid] + red[tid + 1] + red[tid + 2] + red[tid + 3] + __ldg(&Tb[d]);
        t = 1.0f / (1.0f + expf(-t));
        float un = (1.0f - t) * u_sh[d] + o_sh[d] * t;
        g_u[b * DIM + d] = un;
        if (h == HOPS - 1) g_uh[b * DIM + d] = __float2half(un);
    }
}

// ---------------- a_hat[b,v] = sum_d u[b,d]*C3[v,d] via wmma fp16 -------------
__global__ __launch_bounds__(256, 2)
void out_gemm(const float* __restrict__ C3, float* __restrict__ out) {
    extern __shared__ __half sh[];
    __half* As = sh;                 // C3 tile as fp16 [128][128]
    __half* Bs = sh + 128 * 128;     // uh            [128][128]

    int tid = threadIdx.x;
    int wid = tid >> 5;
    int v0  = blockIdx.x * 128;

    for (int i = tid; i < 128 * 32; i += 256) {
        int row = i >> 5, seg = i & 31;
        if (v0 + row < VOCAB) {
            float4 f = __ldg((const float4*)&C3[(ll)(v0 + row) * DIM + seg * 4]);
            __half2 h0 = __floats2half2_rn(f.x, f.y);
            __half2 h1 = __floats2half2_rn(f.z, f.w);
            uint2 st;
            st.x = *(unsigned*)&h0; st.y = *(unsigned*)&h1;
            *(uint2*)&As[row * 128 + seg * 4] = st;
        }
    }
    for (int i = tid; i < 128 * 16; i += 256)
        ((uint4*)Bs)[i] = __ldg(((const uint4*)g_uh) + i);
    __syncthreads();

    wmma::fragment<wmma::accumulator, 16, 16, 16, float> acc[8];
#pragma unroll
    for (int n = 0; n < 8; ++n) wmma::fill_fragment(acc[n], 0.0f);

#pragma unroll
    for (int kt = 0; kt < 8; ++kt) {
        wmma::fragment<wmma::matrix_a, 16, 16, 16, __half, wmma::row_major> af;
        wmma::load_matrix_sync(af, As + (wid * 16) * 128 + kt * 16, 128);
#pragma unroll
        for (int n = 0; n < 8; ++n) {
            wmma::fragment<wmma::matrix_b, 16, 16, 16, __half, wmma::col_major> bf;
            wmma::load_matrix_sync(bf, Bs + (n * 16) * 128 + kt * 16, 128);
            wmma::mma_sync(acc[n], af, bf, acc[n]);
        }
    }

    if (v0 + wid * 16 + 16 <= VOCAB) {
#pragma unroll
        for (int n = 0; n < 8; ++n)
            wmma::store_matrix_sync(out + (ll)(n * 16) * VOCAB + v0 + wid * 16,
                                    acc[n], VOCAB, wmma::mem_col_major);
    }
}

// ---------------- launch: fork-join DAG so hops overlap the gather ------------
extern "C" void kernel_launch(void* const* d_in, const int* in_sizes, int n_in,
                              void* d_out, int out_size) {
    const void*  story = d_in[0];                 // [B,M,S] int32 or int64
    const void*  query = d_in[1];                 // [B,S]
    const float* C     = (const float*)d_in[2];   // [4,V,D]
    const float* Tw    = (const float*)d_in[3];   // [D,D]
    const float* Tb    = (const float*)d_in[4];   // [D]
    float* out = (float*)d_out;                   // [B,V]

    cudaFuncSetAttribute(out_gemm, cudaFuncAttributeMaxDynamicSharedMemorySize,
                         2 * 128 * 128 * (int)sizeof(__half));

    // side stream + events (created per call; host-side, not graph nodes).
    // Not destroyed: capture still references them when we return (2 calls total).
    cudaStream_t s1;
    cudaStreamCreateWithFlags(&s1, cudaStreamNonBlocking);
    cudaEvent_t ef, e1, e2, e3, ej;
    cudaEventCreateWithFlags(&ef, cudaEventDisableTiming);
    cudaEventCreateWithFlags(&e1, cudaEventDisableTiming);
    cudaEventCreateWithFlags(&e2, cudaEventDisableTiming);
    cudaEventCreateWithFlags(&e3, cudaEventDisableTiming);
    cudaEventCreateWithFlags(&ej, cudaEventDisableTiming);

    float* g_m_ptr;
    cudaGetSymbolAddress((void**)&g_m_ptr, g_m);
    const ll MSTR = (ll)BATCH * MEMSZ * DIM;

    // main stream: sniff -> 4 gather passes (the 191us LTS-bound backbone)
    sniff_kernel<<<1, 256>>>((const int*)story, in_sizes[0]);
    cudaEventRecord(ef, 0);
    cudaStreamWaitEvent(s1, ef, 0);                 // fork (s1 depends on sniff)

    u0_kernel<<<BATCH, 128, 0, s1>>>(query, C);     // overlaps gather pass 0

    m_kernel<<<BATCH * MEMSZ, 128>>>(story, C + 0ll * VOCAB * DIM, g_m_ptr + 0 * MSTR);
    m_kernel<<<BATCH * MEMSZ, 128>>>(story, C + 1ll * VOCAB * DIM, g_m_ptr + 1 * MSTR);
    cudaEventRecord(e1, 0);                         // m0,m1 ready
    m_kernel<<<BATCH * MEMSZ, 128>>>(story, C + 2ll * VOCAB * DIM, g_m_ptr + 2 * MSTR);
    cudaEventRecord(e2, 0);                         // m2 ready
    m_kernel<<<BATCH * MEMSZ, 128>>>(story, C + 3ll * VOCAB * DIM, g_m_ptr + 3 * MSTR);
    cudaEventRecord(e3, 0);                         // m3 ready

    // side stream: hops fire as their tables land (overlap passes 2,3)
    cudaStreamWaitEvent(s1, e1, 0);
    hop_kernel<<<BATCH, 512, 0, s1>>>(0, Tw, Tb);
    cudaStreamWaitEvent(s1, e2, 0);
    hop_kernel<<<BATCH, 512, 0, s1>>>(1, Tw, Tb);
    cudaStreamWaitEvent(s1, e3, 0);
    hop_kernel<<<BATCH, 512, 0, s1>>>(2, Tw, Tb);

    out_gemm<<<(VOCAB + 127) / 128, 256, 2 * 128 * 128 * sizeof(__half), s1>>>(
        C + 3ll * VOCAB * DIM, out);

    cudaEventRecord(ej, s1);
    cudaStreamWaitEvent(0, ej, 0);                  // join back to main stream
}